// round 6
// baseline (speedup 1.0000x reference)
#include <cuda_runtime.h>
#include <cstddef>
#include <cstdint>

// Problem dims
#define BB 32
#define SB 2048
#define DD 256
#define HH 512
#define G4 2048   // 4*H
#define OO 256
#define BH (BB * HH)   // 16384 floats per timestep of h

// ---------------------------------------------------------------------------
// Scratch (device globals: allocation-free per harness rules)
// ---------------------------------------------------------------------------
__device__ float g_xg[(size_t)BB * SB * G4];   // [b][s][4H] input projections
__device__ float g_h [(size_t)SB * BH];        // [t][b][H] hidden states
__device__ unsigned g_bar_cnt;                 // grid barrier state (replay-safe)
__device__ unsigned g_bar_gen;
__device__ float g_dummy_sink;                 // dummy-kernel target

// ---------------------------------------------------------------------------
// f32x2 packed-FMA helpers
// ---------------------------------------------------------------------------
__device__ __forceinline__ void ffma2(unsigned long long& acc, unsigned long long a,
                                      unsigned long long b) {
    asm("fma.rn.f32x2 %0, %1, %2, %0;" : "+l"(acc) : "l"(a), "l"(b));
}
__device__ __forceinline__ unsigned long long dup2(float x) {
    unsigned long long r;
    asm("mov.b64 %0, {%1, %1};" : "=l"(r) : "f"(x));
    return r;
}
__device__ __forceinline__ unsigned long long pack2(float lo, float hi) {
    unsigned long long r;
    asm("mov.b64 %0, {%1, %2};" : "=l"(r) : "f"(lo), "f"(hi));
    return r;
}
__device__ __forceinline__ void unpack2(unsigned long long v, float& lo, float& hi) {
    asm("mov.b64 {%0, %1}, %2;" : "=f"(lo), "=f"(hi) : "l"(v));
}
__device__ __forceinline__ float sigm(float x) { return 1.f / (1.f + __expf(-x)); }

// Tiny launch used only to shift ncu's capture window onto lstm_rec.
__global__ void dummy_k() { if (threadIdx.x == 1024) g_dummy_sink = 1.f; }

// ---------------------------------------------------------------------------
// SGEMM: C[M,N] = A[M,K] @ B[K,N] + bias[N] (row-major fp32), 64x64 tile,
// BK=16, 128 threads, 8x4 register tile, f32x2 inner loop. (unchanged, passing)
// ---------------------------------------------------------------------------
template <bool REMAP>
__global__ __launch_bounds__(128)
void sgemm_f32x2(const float* __restrict__ A, const float* __restrict__ Bm,
                 const float* __restrict__ bias, float* __restrict__ C,
                 int M, int N, int K) {
    __shared__ float As[64 * 16];
    __shared__ float Bs[16 * 64];

    const int tid = threadIdx.x;
    const int tx  = tid & 15;
    const int ty  = tid >> 4;
    const int bn  = blockIdx.x * 64;
    const int bm  = blockIdx.y * 64;

    unsigned long long acc[8][2];
#pragma unroll
    for (int i = 0; i < 8; i++) { acc[i][0] = 0ull; acc[i][1] = 0ull; }

    const int ar = tid >> 2, ac = (tid & 3) * 4;
    const int br = tid >> 4, bc = (tid & 15) * 4;

    for (int k0 = 0; k0 < K; k0 += 16) {
#pragma unroll
        for (int p = 0; p < 2; p++) {
            int row = ar + p * 32;
            *(float4*)(As + row * 16 + ac) =
                *(const float4*)(A + (size_t)(bm + row) * K + k0 + ac);
        }
#pragma unroll
        for (int p = 0; p < 2; p++) {
            int row = br + p * 8;
            *(float4*)(Bs + row * 64 + bc) =
                *(const float4*)(Bm + (size_t)(k0 + row) * N + bn + bc);
        }
        __syncthreads();

#pragma unroll
        for (int kk = 0; kk < 16; kk++) {
            ulonglong2 w = *(const ulonglong2*)(Bs + kk * 64 + tx * 4);
#pragma unroll
            for (int im = 0; im < 8; im++) {
                unsigned long long ad = dup2(As[(ty * 8 + im) * 16 + kk]);
                ffma2(acc[im][0], ad, w.x);
                ffma2(acc[im][1], ad, w.y);
            }
        }
        __syncthreads();
    }

    float4 bvec = *(const float4*)(bias + bn + tx * 4);
#pragma unroll
    for (int im = 0; im < 8; im++) {
        int row = bm + ty * 8 + im;
        float x0, x1, x2, x3;
        unpack2(acc[im][0], x0, x1);
        unpack2(acc[im][1], x2, x3);
        float4 o = make_float4(x0 + bvec.x, x1 + bvec.y, x2 + bvec.z, x3 + bvec.w);
        size_t orow = REMAP ? ((size_t)(row & 31) * SB + (size_t)(row >> 5))
                            : (size_t)row;
        *(float4*)(C + orow * N + bn + tx * 4) = o;
    }
}

// ---------------------------------------------------------------------------
// Persistent LSTM recurrence, v4 = R4-passing kernel with a bounded-spin
// barrier poll. 128 CTAs x 256 threads. CTA owns 4 hidden units; Wh slice
// (32KB) in SMEM for all 2048 steps. Split-K x2, register-pipelined inner
// loop, dual accumulator sets, xg prefetched one step ahead.
// Barrier wait: volatile-load spin with a nanosleep fallback only after 4096
// failed polls — fast (~1 poll) detection in healthy runs, still yields under
// pathological stalls (tight sleep-free spins correlated with container
// failures in R3/R5; pure nanosleep polling has us-scale overshoot).
// ---------------------------------------------------------------------------
#define HS_STRIDE 516
#define KHALF 256

__global__ __launch_bounds__(256, 1)
void lstm_rec(const float* __restrict__ Wh) {
    extern __shared__ float sm[];
    float* Whs = sm;                         // [512][16]  (8192 floats)
    float* hs  = sm + HH * 16;               // [32][516]  (16512 floats)
    float* red = hs + 32 * HS_STRIDE;        // [128][4]   (512 floats)

    const int tid = threadIdx.x;
    const int kh  = tid >> 7;                // k-half 0/1
    const int r   = tid & 127;
    const int tm  = r >> 2;                  // batch row 0..31
    const int tn  = r & 3;                   // local unit 0..3
    const int j0  = blockIdx.x * 4;
    const int j   = j0 + tn;
    const unsigned nb = gridDim.x;

    // Load Wh slice, layout Whs[k*16 + u*4 + q] = Wh[k][q*HH + j0 + u]
    for (int idx = tid; idx < HH * 16; idx += 256) {
        int k = idx >> 4, c = idx & 15, u = c >> 2, q = c & 3;
        Whs[idx] = Wh[(size_t)k * G4 + q * HH + j0 + u];
    }

    float cst = 0.f;
    const float* hrow = hs + tm * HS_STRIDE + kh * KHALF;
    const float* wcol = Whs + (kh * KHALF) * 16 + tn * 4;
    float* myred = red + r * 4;

    // xg prefetch registers (kh=0 only)
    float xi = 0.f, xf = 0.f, xG = 0.f, xo = 0.f;
    if (kh == 0) {
        const float* xgp = g_xg + ((size_t)tm * SB + 0) * G4;
        xi = __ldcg(xgp + j);          xf = __ldcg(xgp + HH + j);
        xG = __ldcg(xgp + 2 * HH + j); xo = __ldcg(xgp + 3 * HH + j);
    }

    for (int t = 0; t < SB; t++) {
        // ---- stage h[t-1] into SMEM (padded stride, conflict-free) ----
        if (t == 0) {
            float4 z = make_float4(0.f, 0.f, 0.f, 0.f);
            for (int i = tid; i < BH / 4; i += 256) {
                int m = i >> 7, c = i & 127;
                *(float4*)(hs + m * HS_STRIDE + (c << 2)) = z;
            }
        } else {
            const float4* src = (const float4*)(g_h + (size_t)(t - 1) * BH);
            for (int i = tid; i < BH / 4; i += 256) {
                int m = i >> 7, c = i & 127;
                *(float4*)(hs + m * HS_STRIDE + (c << 2)) = __ldcg(src + m * 128 + c);
            }
        }
        __syncthreads();

        // ---- per-step GEMV: 4 gate dots over this thread's k-half ----
        unsigned long long a01_0, a23_0, a01_1 = 0ull, a23_1 = 0ull;
        if (kh == 0) { a01_0 = pack2(xi, xf); a23_0 = pack2(xG, xo); }
        else         { a01_0 = 0ull;          a23_0 = 0ull; }

        // preload group 0 (4 k values)
        float4 h0 = *(const float4*)(hrow);
        ulonglong2 wA0 = *(const ulonglong2*)(wcol);
        ulonglong2 wB0 = *(const ulonglong2*)(wcol + 16);
        ulonglong2 wC0 = *(const ulonglong2*)(wcol + 32);
        ulonglong2 wD0 = *(const ulonglong2*)(wcol + 48);

#pragma unroll 2
        for (int g = 0; g < KHALF / 4; g += 2) {
            // prefetch group g+1
            const float* hp1 = hrow + (g + 1) * 4;
            const float* wp1 = wcol + (g + 1) * 64;
            float4 h1 = *(const float4*)(hp1);
            ulonglong2 wA1 = *(const ulonglong2*)(wp1);
            ulonglong2 wB1 = *(const ulonglong2*)(wp1 + 16);
            ulonglong2 wC1 = *(const ulonglong2*)(wp1 + 32);
            ulonglong2 wD1 = *(const ulonglong2*)(wp1 + 48);

            // FMA group g -> accumulator set 0
            { unsigned long long d = dup2(h0.x); ffma2(a01_0, d, wA0.x); ffma2(a23_0, d, wA0.y); }
            { unsigned long long d = dup2(h0.y); ffma2(a01_0, d, wB0.x); ffma2(a23_0, d, wB0.y); }
            { unsigned long long d = dup2(h0.z); ffma2(a01_0, d, wC0.x); ffma2(a23_0, d, wC0.y); }
            { unsigned long long d = dup2(h0.w); ffma2(a01_0, d, wD0.x); ffma2(a23_0, d, wD0.y); }

            // prefetch group g+2 (over-reads one group at the end: lands in
            // the padded hs row tail / adjacent SMEM region, never consumed)
            const float* hp2 = hrow + (g + 2) * 4;
            const float* wp2 = wcol + (g + 2) * 64;
            h0  = *(const float4*)(hp2);
            wA0 = *(const ulonglong2*)(wp2);
            wB0 = *(const ulonglong2*)(wp2 + 16);
            wC0 = *(const ulonglong2*)(wp2 + 32);
            wD0 = *(const ulonglong2*)(wp2 + 48);

            // FMA group g+1 -> accumulator set 1
            { unsigned long long d = dup2(h1.x); ffma2(a01_1, d, wA1.x); ffma2(a23_1, d, wA1.y); }
            { unsigned long long d = dup2(h1.y); ffma2(a01_1, d, wB1.x); ffma2(a23_1, d, wB1.y); }
            { unsigned long long d = dup2(h1.z); ffma2(a01_1, d, wC1.x); ffma2(a23_1, d, wC1.y); }
            { unsigned long long d = dup2(h1.w); ffma2(a01_1, d, wD1.x); ffma2(a23_1, d, wD1.y); }
        }

        // combine accumulator sets -> 4 scalar gate partials
        float gi0, gf0, gg0, go0, gi1, gf1, gg1, go1;
        unpack2(a01_0, gi0, gf0); unpack2(a23_0, gg0, go0);
        unpack2(a01_1, gi1, gf1); unpack2(a23_1, gg1, go1);
        float gi = gi0 + gi1, gf = gf0 + gf1, gg = gg0 + gg1, go = go0 + go1;

        // ---- cross-k reduction + cell update ----
        if (kh == 1) *(float4*)myred = make_float4(gi, gf, gg, go);
        __syncthreads();
        if (kh == 0) {
            float4 p = *(const float4*)myred;
            gi += p.x; gf += p.y; gg += p.z; go += p.w;
            float si = sigm(gi), sf = sigm(gf), so = sigm(go);
            cst = sf * cst + si * tanhf(gg);
            float hn = so * tanhf(cst);
            __stcg(g_h + (size_t)t * BH + (size_t)tm * HH + j, hn);

            // prefetch xg for step t+1 (hidden behind the barrier)
            int tn1 = (t + 1 < SB) ? (t + 1) : (SB - 1);
            const float* xgp = g_xg + ((size_t)tm * SB + tn1) * G4;
            xi = __ldcg(xgp + j);          xf = __ldcg(xgp + HH + j);
            xG = __ldcg(xgp + 2 * HH + j); xo = __ldcg(xgp + 3 * HH + j);
        }

        // ---- grid barrier (sense-reversing; bounded spin + sleep fallback) ----
        __threadfence();
        __syncthreads();
        if (tid == 0) {
            volatile unsigned* vgen = &g_bar_gen;
            unsigned g = *vgen;
            unsigned old = atomicAdd(&g_bar_cnt, 1u);
            if (old == nb - 1u) {
                atomicExch(&g_bar_cnt, 0u);
                __threadfence();
                atomicAdd(&g_bar_gen, 1u);
            } else {
                int spins = 0;
                while (*vgen == g) {
                    if (++spins >= 4096) { __nanosleep(64); spins = 0; }
                }
            }
        }
        __syncthreads();
    }
}

// ---------------------------------------------------------------------------
// Launch
// ---------------------------------------------------------------------------
extern "C" void kernel_launch(void* const* d_in, const int* in_sizes, int n_in,
                              void* d_out, int out_size) {
    const float *x = nullptr, *Wx = nullptr, *Wh = nullptr,
                *b = nullptr, *Wo = nullptr, *bo = nullptr;
    for (int i = 0; i < n_in; i++) {
        switch (in_sizes[i]) {
            case BB * SB * DD: x  = (const float*)d_in[i]; break;
            case DD * G4:      Wx = (const float*)d_in[i]; break;
            case HH * G4:      Wh = (const float*)d_in[i]; break;
            case G4:           b  = (const float*)d_in[i]; break;
            case HH * OO:      Wo = (const float*)d_in[i]; break;
            case OO:           bo = (const float*)d_in[i]; break;
        }
    }

    float* xg;   cudaGetSymbolAddress((void**)&xg, g_xg);
    float* hall; cudaGetSymbolAddress((void**)&hall, g_h);

    // 1) xg = x @ Wx + b
    {
        dim3 grid(G4 / 64, (BB * SB) / 64);
        sgemm_f32x2<false><<<grid, 128>>>(x, Wx, b, xg, BB * SB, G4, DD);
    }

    // launches 1-4: dummies so ncu's "-s 5 -c 1" window captures lstm_rec
    dummy_k<<<1, 32>>>();
    dummy_k<<<1, 32>>>();
    dummy_k<<<1, 32>>>();
    dummy_k<<<1, 32>>>();

    // 2) persistent recurrence (launch index 5)
    {
        int smem_bytes = (HH * 16 + 32 * HS_STRIDE + 128 * 4) * (int)sizeof(float);
        cudaFuncSetAttribute(lstm_rec, cudaFuncAttributeMaxDynamicSharedMemorySize,
                             smem_bytes);
        lstm_rec<<<HH / 4, 256, smem_bytes>>>(Wh);
    }

    // 3) y = h @ Wo + bo with [t][b] -> [b][t] remap
    {
        dim3 grid(OO / 64, (BB * SB) / 64);
        sgemm_f32x2<true><<<grid, 128>>>(hall, Wo, bo, (float*)d_out,
                                         BB * SB, OO, HH);
    }
}

// round 7
// speedup vs baseline: 1.3486x; 1.3486x over previous
#include <cuda_runtime.h>
#include <cstddef>
#include <cstdint>

// Problem dims
#define BB 32
#define SB 2048
#define DD 256
#define HH 512
#define G4 2048   // 4*H
#define OO 256
#define BH (BB * HH)   // 16384 floats per timestep of h

// ---------------------------------------------------------------------------
// Scratch (device globals: allocation-free per harness rules)
// ---------------------------------------------------------------------------
__device__ float g_xg[(size_t)BB * SB * G4];   // [b][s][4H] input projections
__device__ float g_h [(size_t)SB * BH];        // [t][b][H] hidden states
__device__ unsigned g_bar_cnt;                 // grid barrier state (replay-safe)
__device__ unsigned g_bar_gen;
__device__ float g_dummy_sink;                 // dummy-kernel target

// ---------------------------------------------------------------------------
// f32x2 packed-FMA helpers
// ---------------------------------------------------------------------------
__device__ __forceinline__ void ffma2(unsigned long long& acc, unsigned long long a,
                                      unsigned long long b) {
    asm("fma.rn.f32x2 %0, %1, %2, %0;" : "+l"(acc) : "l"(a), "l"(b));
}
__device__ __forceinline__ unsigned long long dup2(float x) {
    unsigned long long r;
    asm("mov.b64 %0, {%1, %1};" : "=l"(r) : "f"(x));
    return r;
}
__device__ __forceinline__ unsigned long long pack2(float lo, float hi) {
    unsigned long long r;
    asm("mov.b64 %0, {%1, %2};" : "=l"(r) : "f"(lo), "f"(hi));
    return r;
}
__device__ __forceinline__ void unpack2(unsigned long long v, float& lo, float& hi) {
    asm("mov.b64 {%0, %1}, %2;" : "=f"(lo), "=f"(hi) : "l"(v));
}
__device__ __forceinline__ float sigm(float x) { return 1.f / (1.f + __expf(-x)); }

// Tiny launch used only to shift ncu's capture window onto lstm_rec.
__global__ void dummy_k() { if (threadIdx.x == 1024) g_dummy_sink = 1.f; }

// ---------------------------------------------------------------------------
// SGEMM: C[M,N] = A[M,K] @ B[K,N] + bias[N] (row-major fp32), 64x64 tile,
// BK=16, 128 threads, 8x4 register tile, f32x2 inner loop. (unchanged, passing)
// ---------------------------------------------------------------------------
template <bool REMAP>
__global__ __launch_bounds__(128)
void sgemm_f32x2(const float* __restrict__ A, const float* __restrict__ Bm,
                 const float* __restrict__ bias, float* __restrict__ C,
                 int M, int N, int K) {
    __shared__ float As[64 * 16];
    __shared__ float Bs[16 * 64];

    const int tid = threadIdx.x;
    const int tx  = tid & 15;
    const int ty  = tid >> 4;
    const int bn  = blockIdx.x * 64;
    const int bm  = blockIdx.y * 64;

    unsigned long long acc[8][2];
#pragma unroll
    for (int i = 0; i < 8; i++) { acc[i][0] = 0ull; acc[i][1] = 0ull; }

    const int ar = tid >> 2, ac = (tid & 3) * 4;
    const int br = tid >> 4, bc = (tid & 15) * 4;

    for (int k0 = 0; k0 < K; k0 += 16) {
#pragma unroll
        for (int p = 0; p < 2; p++) {
            int row = ar + p * 32;
            *(float4*)(As + row * 16 + ac) =
                *(const float4*)(A + (size_t)(bm + row) * K + k0 + ac);
        }
#pragma unroll
        for (int p = 0; p < 2; p++) {
            int row = br + p * 8;
            *(float4*)(Bs + row * 64 + bc) =
                *(const float4*)(Bm + (size_t)(k0 + row) * N + bn + bc);
        }
        __syncthreads();

#pragma unroll
        for (int kk = 0; kk < 16; kk++) {
            ulonglong2 w = *(const ulonglong2*)(Bs + kk * 64 + tx * 4);
#pragma unroll
            for (int im = 0; im < 8; im++) {
                unsigned long long ad = dup2(As[(ty * 8 + im) * 16 + kk]);
                ffma2(acc[im][0], ad, w.x);
                ffma2(acc[im][1], ad, w.y);
            }
        }
        __syncthreads();
    }

    float4 bvec = *(const float4*)(bias + bn + tx * 4);
#pragma unroll
    for (int im = 0; im < 8; im++) {
        int row = bm + ty * 8 + im;
        float x0, x1, x2, x3;
        unpack2(acc[im][0], x0, x1);
        unpack2(acc[im][1], x2, x3);
        float4 o = make_float4(x0 + bvec.x, x1 + bvec.y, x2 + bvec.z, x3 + bvec.w);
        size_t orow = REMAP ? ((size_t)(row & 31) * SB + (size_t)(row >> 5))
                            : (size_t)row;
        *(float4*)(C + orow * N + bn + tx * 4) = o;
    }
}

// ---------------------------------------------------------------------------
// Persistent LSTM recurrence, v5: re-tiled GEMV to cut SMEM crossbar traffic.
// 128 CTAs x 256 threads. CTA owns 4 hidden units (16 gate cols); Wh slice
// (32KB) in SMEM for all 2048 steps.
// Thread tile: 4 batches x 1 unit (4 gates) x 64 k. Split-K=8, one k-slice
// per warp. Per 4k group: 4 h-float4 + 4 weight-LDS.128 = 8 LDS.128 for 64
// MACs (vs v4's 5 per 16) -> SM-wide LDS.128 per step drops 2560 -> 1024.
// Partials reduced 8-way through a 16KB SMEM buffer; threads 0-127 hold the
// c-state and do the cell update (xg seeds folded in there).
// ---------------------------------------------------------------------------
#define HS_STRIDE 516
#define WHS_F (HH * 16)                 // 8192 floats
#define HS_F  (32 * HS_STRIDE)          // 16512 floats
#define RED_F (8 * 512)                 // 4096 floats

__global__ __launch_bounds__(256, 1)
void lstm_rec(const float* __restrict__ Wh) {
    extern __shared__ float sm[];
    float* Whs = sm;                     // [512][16]: [k][u*4+q]
    float* hs  = sm + WHS_F;             // [32][HS_STRIDE]
    float* red = sm + WHS_F + HS_F;      // [8 s][32 tm * 16 gatecols]

    const int tid = threadIdx.x;
    const int u   = tid & 3;             // unit 0..3
    const int tmg = (tid >> 2) & 7;      // batch group (4 rows each)
    const int s   = tid >> 5;            // k-slice 0..7 (== warp id)
    const int tmb = tmg * 4;
    const int k0  = s * 64;
    const int j0  = blockIdx.x * 4;
    const unsigned nb = gridDim.x;

    // Load Wh slice: Whs[k*16 + uu*4 + q] = Wh[k][q*HH + j0 + uu]
    for (int idx = tid; idx < WHS_F; idx += 256) {
        int k = idx >> 4, c = idx & 15, uu = c >> 2, q = c & 3;
        Whs[idx] = Wh[(size_t)k * G4 + q * HH + j0 + uu];
    }

    // Update-thread state (threads 0..127: thread r handles (tm=r>>2, unit=r&3))
    float cst = 0.f;
    const int utm = tid >> 2;            // valid for tid<128
    const int uj  = j0 + (tid & 3);
    float xi = 0.f, xf = 0.f, xG = 0.f, xo = 0.f;
    if (tid < 128) {
        const float* xgp = g_xg + ((size_t)utm * SB + 0) * G4;
        xi = __ldcg(xgp + uj);          xf = __ldcg(xgp + HH + uj);
        xG = __ldcg(xgp + 2 * HH + uj); xo = __ldcg(xgp + 3 * HH + uj);
    }

    const float* hp0 = hs + (tmb + 0) * HS_STRIDE + k0;
    const float* hp1 = hs + (tmb + 1) * HS_STRIDE + k0;
    const float* hp2 = hs + (tmb + 2) * HS_STRIDE + k0;
    const float* hp3 = hs + (tmb + 3) * HS_STRIDE + k0;
    const float* wp  = Whs + k0 * 16 + u * 4;
    float* rwr = red + s * 512 + tmb * 16 + u * 4;   // this thread's partials

    for (int t = 0; t < SB; t++) {
        // ---- stage h[t-1] into SMEM (padded stride, conflict-free) ----
        if (t == 0) {
            float4 z = make_float4(0.f, 0.f, 0.f, 0.f);
            for (int i = tid; i < BH / 4; i += 256) {
                int m = i >> 7, c = i & 127;
                *(float4*)(hs + m * HS_STRIDE + (c << 2)) = z;
            }
        } else {
            const float4* src = (const float4*)(g_h + (size_t)(t - 1) * BH);
            for (int i = tid; i < BH / 4; i += 256) {
                int m = i >> 7, c = i & 127;
                *(float4*)(hs + m * HS_STRIDE + (c << 2)) = __ldcg(src + m * 128 + c);
            }
        }
        __syncthreads();

        // ---- GEMV: 4 batches x 4 gates over k in [k0, k0+64) ----
        unsigned long long a00 = 0, a01 = 0, a10 = 0, a11 = 0,
                           a20 = 0, a21 = 0, a30 = 0, a31 = 0;

#pragma unroll 4
        for (int kk = 0; kk < 64; kk += 4) {
            float4 ha = *(const float4*)(hp0 + kk);
            float4 hb = *(const float4*)(hp1 + kk);
            float4 hc = *(const float4*)(hp2 + kk);
            float4 hd = *(const float4*)(hp3 + kk);
            ulonglong2 w0 = *(const ulonglong2*)(wp + (kk + 0) * 16);
            ulonglong2 w1 = *(const ulonglong2*)(wp + (kk + 1) * 16);
            ulonglong2 w2 = *(const ulonglong2*)(wp + (kk + 2) * 16);
            ulonglong2 w3 = *(const ulonglong2*)(wp + (kk + 3) * 16);

            { unsigned long long d = dup2(ha.x); ffma2(a00, d, w0.x); ffma2(a01, d, w0.y); }
            { unsigned long long d = dup2(hb.x); ffma2(a10, d, w0.x); ffma2(a11, d, w0.y); }
            { unsigned long long d = dup2(hc.x); ffma2(a20, d, w0.x); ffma2(a21, d, w0.y); }
            { unsigned long long d = dup2(hd.x); ffma2(a30, d, w0.x); ffma2(a31, d, w0.y); }

            { unsigned long long d = dup2(ha.y); ffma2(a00, d, w1.x); ffma2(a01, d, w1.y); }
            { unsigned long long d = dup2(hb.y); ffma2(a10, d, w1.x); ffma2(a11, d, w1.y); }
            { unsigned long long d = dup2(hc.y); ffma2(a20, d, w1.x); ffma2(a21, d, w1.y); }
            { unsigned long long d = dup2(hd.y); ffma2(a30, d, w1.x); ffma2(a31, d, w1.y); }

            { unsigned long long d = dup2(ha.z); ffma2(a00, d, w2.x); ffma2(a01, d, w2.y); }
            { unsigned long long d = dup2(hb.z); ffma2(a10, d, w2.x); ffma2(a11, d, w2.y); }
            { unsigned long long d = dup2(hc.z); ffma2(a20, d, w2.x); ffma2(a21, d, w2.y); }
            { unsigned long long d = dup2(hd.z); ffma2(a30, d, w2.x); ffma2(a31, d, w2.y); }

            { unsigned long long d = dup2(ha.w); ffma2(a00, d, w3.x); ffma2(a01, d, w3.y); }
            { unsigned long long d = dup2(hb.w); ffma2(a10, d, w3.x); ffma2(a11, d, w3.y); }
            { unsigned long long d = dup2(hc.w); ffma2(a20, d, w3.x); ffma2(a21, d, w3.y); }
            { unsigned long long d = dup2(hd.w); ffma2(a30, d, w3.x); ffma2(a31, d, w3.y); }
        }

        // ---- write partials: red[s][(tmb+i)*16 + u*4 .. +3] ----
        {
            float p0, p1, p2, p3;
            unpack2(a00, p0, p1); unpack2(a01, p2, p3);
            *(float4*)(rwr + 0 * 16) = make_float4(p0, p1, p2, p3);
            unpack2(a10, p0, p1); unpack2(a11, p2, p3);
            *(float4*)(rwr + 1 * 16) = make_float4(p0, p1, p2, p3);
            unpack2(a20, p0, p1); unpack2(a21, p2, p3);
            *(float4*)(rwr + 2 * 16) = make_float4(p0, p1, p2, p3);
            unpack2(a30, p0, p1); unpack2(a31, p2, p3);
            *(float4*)(rwr + 3 * 16) = make_float4(p0, p1, p2, p3);
        }
        __syncthreads();

        // ---- 8-way reduction + cell update (threads 0..127) ----
        if (tid < 128) {
            const float* q = red + tid * 4;   // == utm*16 + uu*4
            float gi = xi, gf = xf, gg = xG, go = xo;
#pragma unroll
            for (int ss = 0; ss < 8; ss++) {
                float4 p = *(const float4*)(q + ss * 512);
                gi += p.x; gf += p.y; gg += p.z; go += p.w;
            }
            float si = sigm(gi), sf = sigm(gf), so = sigm(go);
            cst = sf * cst + si * tanhf(gg);
            float hn = so * tanhf(cst);
            __stcg(g_h + (size_t)t * BH + (size_t)utm * HH + uj, hn);

            // prefetch xg for step t+1 (hidden behind the barrier)
            int tn1 = (t + 1 < SB) ? (t + 1) : (SB - 1);
            const float* xgp = g_xg + ((size_t)utm * SB + tn1) * G4;
            xi = __ldcg(xgp + uj);          xf = __ldcg(xgp + HH + uj);
            xG = __ldcg(xgp + 2 * HH + uj); xo = __ldcg(xgp + 3 * HH + uj);
        }

        // ---- grid barrier (sense-reversing; bounded spin + sleep fallback) ----
        __threadfence();
        __syncthreads();
        if (tid == 0) {
            volatile unsigned* vgen = &g_bar_gen;
            unsigned g = *vgen;
            unsigned old = atomicAdd(&g_bar_cnt, 1u);
            if (old == nb - 1u) {
                atomicExch(&g_bar_cnt, 0u);
                __threadfence();
                atomicAdd(&g_bar_gen, 1u);
            } else {
                int spins = 0;
                while (*vgen == g) {
                    if (++spins >= 4096) { __nanosleep(64); spins = 0; }
                }
            }
        }
        __syncthreads();
    }
}

// ---------------------------------------------------------------------------
// Launch
// ---------------------------------------------------------------------------
extern "C" void kernel_launch(void* const* d_in, const int* in_sizes, int n_in,
                              void* d_out, int out_size) {
    const float *x = nullptr, *Wx = nullptr, *Wh = nullptr,
                *b = nullptr, *Wo = nullptr, *bo = nullptr;
    for (int i = 0; i < n_in; i++) {
        switch (in_sizes[i]) {
            case BB * SB * DD: x  = (const float*)d_in[i]; break;
            case DD * G4:      Wx = (const float*)d_in[i]; break;
            case HH * G4:      Wh = (const float*)d_in[i]; break;
            case G4:           b  = (const float*)d_in[i]; break;
            case HH * OO:      Wo = (const float*)d_in[i]; break;
            case OO:           bo = (const float*)d_in[i]; break;
        }
    }

    float* xg;   cudaGetSymbolAddress((void**)&xg, g_xg);
    float* hall; cudaGetSymbolAddress((void**)&hall, g_h);

    // 1) xg = x @ Wx + b
    {
        dim3 grid(G4 / 64, (BB * SB) / 64);
        sgemm_f32x2<false><<<grid, 128>>>(x, Wx, b, xg, BB * SB, G4, DD);
    }

    // 2 dummies so ncu's "-s 5 -c 1" window (2 hidden leading launches
    // observed) lands exactly on lstm_rec.
    dummy_k<<<1, 32>>>();
    dummy_k<<<1, 32>>>();

    // 2) persistent recurrence
    {
        int smem_bytes = (WHS_F + HS_F + RED_F) * (int)sizeof(float); // 115200
        cudaFuncSetAttribute(lstm_rec, cudaFuncAttributeMaxDynamicSharedMemorySize,
                             smem_bytes);
        lstm_rec<<<HH / 4, 256, smem_bytes>>>(Wh);
    }

    // 3) y = h @ Wo + bo with [t][b] -> [b][t] remap
    {
        dim3 grid(OO / 64, (BB * SB) / 64);
        sgemm_f32x2<true><<<grid, 128>>>(hall, Wo, bo, (float*)d_out,
                                         BB * SB, OO, HH);
    }
}

// round 8
// speedup vs baseline: 1.3494x; 1.0006x over previous
#include <cuda_runtime.h>
#include <cstddef>
#include <cstdint>

// Problem dims
#define BB 32
#define SB 2048
#define DD 256
#define HH 512
#define G4 2048   // 4*H
#define OO 256
#define BH (BB * HH)   // 16384 floats per timestep of h

// ---------------------------------------------------------------------------
// Scratch (device globals: allocation-free per harness rules)
// ---------------------------------------------------------------------------
__device__ float g_xg[(size_t)BB * SB * G4];   // [b][s][4H] input projections
__device__ float g_h [(size_t)SB * BH];        // [t][b][H] hidden states
__device__ unsigned g_bar_cnt;                 // grid barrier state (replay-safe)
__device__ unsigned g_bar_gen;
__device__ float g_dummy_sink;                 // dummy-kernel target

// ---------------------------------------------------------------------------
// f32x2 packed-FMA helpers
// ---------------------------------------------------------------------------
__device__ __forceinline__ void ffma2(unsigned long long& acc, unsigned long long a,
                                      unsigned long long b) {
    asm("fma.rn.f32x2 %0, %1, %2, %0;" : "+l"(acc) : "l"(a), "l"(b));
}
__device__ __forceinline__ unsigned long long dup2(float x) {
    unsigned long long r;
    asm("mov.b64 %0, {%1, %1};" : "=l"(r) : "f"(x));
    return r;
}
__device__ __forceinline__ unsigned long long pack2(float lo, float hi) {
    unsigned long long r;
    asm("mov.b64 %0, {%1, %2};" : "=l"(r) : "f"(lo), "f"(hi));
    return r;
}
__device__ __forceinline__ void unpack2(unsigned long long v, float& lo, float& hi) {
    asm("mov.b64 {%0, %1}, %2;" : "=f"(lo), "=f"(hi) : "l"(v));
}
__device__ __forceinline__ float sigm(float x) { return 1.f / (1.f + __expf(-x)); }

// Tiny launch used only to shift ncu's capture window onto lstm_rec.
__global__ void dummy_k() { if (threadIdx.x == 1024) g_dummy_sink = 1.f; }

// ---------------------------------------------------------------------------
// SGEMM: C[M,N] = A[M,K] @ B[K,N] + bias[N] (row-major fp32), 64x64 tile,
// BK=16, 128 threads, 8x4 register tile, f32x2 inner loop. (unchanged, passing)
// ---------------------------------------------------------------------------
template <bool REMAP>
__global__ __launch_bounds__(128)
void sgemm_f32x2(const float* __restrict__ A, const float* __restrict__ Bm,
                 const float* __restrict__ bias, float* __restrict__ C,
                 int M, int N, int K) {
    __shared__ float As[64 * 16];
    __shared__ float Bs[16 * 64];

    const int tid = threadIdx.x;
    const int tx  = tid & 15;
    const int ty  = tid >> 4;
    const int bn  = blockIdx.x * 64;
    const int bm  = blockIdx.y * 64;

    unsigned long long acc[8][2];
#pragma unroll
    for (int i = 0; i < 8; i++) { acc[i][0] = 0ull; acc[i][1] = 0ull; }

    const int ar = tid >> 2, ac = (tid & 3) * 4;
    const int br = tid >> 4, bc = (tid & 15) * 4;

    for (int k0 = 0; k0 < K; k0 += 16) {
#pragma unroll
        for (int p = 0; p < 2; p++) {
            int row = ar + p * 32;
            *(float4*)(As + row * 16 + ac) =
                *(const float4*)(A + (size_t)(bm + row) * K + k0 + ac);
        }
#pragma unroll
        for (int p = 0; p < 2; p++) {
            int row = br + p * 8;
            *(float4*)(Bs + row * 64 + bc) =
                *(const float4*)(Bm + (size_t)(k0 + row) * N + bn + bc);
        }
        __syncthreads();

#pragma unroll
        for (int kk = 0; kk < 16; kk++) {
            ulonglong2 w = *(const ulonglong2*)(Bs + kk * 64 + tx * 4);
#pragma unroll
            for (int im = 0; im < 8; im++) {
                unsigned long long ad = dup2(As[(ty * 8 + im) * 16 + kk]);
                ffma2(acc[im][0], ad, w.x);
                ffma2(acc[im][1], ad, w.y);
            }
        }
        __syncthreads();
    }

    float4 bvec = *(const float4*)(bias + bn + tx * 4);
#pragma unroll
    for (int im = 0; im < 8; im++) {
        int row = bm + ty * 8 + im;
        float x0, x1, x2, x3;
        unpack2(acc[im][0], x0, x1);
        unpack2(acc[im][1], x2, x3);
        float4 o = make_float4(x0 + bvec.x, x1 + bvec.y, x2 + bvec.z, x3 + bvec.w);
        size_t orow = REMAP ? ((size_t)(row & 31) * SB + (size_t)(row >> 5))
                            : (size_t)row;
        *(float4*)(C + orow * N + bn + tx * 4) = o;
    }
}

// ---------------------------------------------------------------------------
// Persistent LSTM recurrence, v5: re-tiled GEMV to cut SMEM crossbar traffic.
// 128 CTAs x 256 threads. CTA owns 4 hidden units (16 gate cols); Wh slice
// (32KB) in SMEM for all 2048 steps.
// Thread tile: 4 batches x 1 unit (4 gates) x 64 k. Split-K=8, one k-slice
// per warp. Per 4k group: 4 h-float4 + 4 weight-LDS.128 = 8 LDS.128 for 64
// MACs (vs v4's 5 per 16) -> SM-wide LDS.128 per step drops 2560 -> 1024.
// Partials reduced 8-way through a 16KB SMEM buffer; threads 0-127 hold the
// c-state and do the cell update (xg seeds folded in there).
// ---------------------------------------------------------------------------
#define HS_STRIDE 516
#define WHS_F (HH * 16)                 // 8192 floats
#define HS_F  (32 * HS_STRIDE)          // 16512 floats
#define RED_F (8 * 512)                 // 4096 floats

__global__ __launch_bounds__(256, 1)
void lstm_rec(const float* __restrict__ Wh) {
    extern __shared__ float sm[];
    float* Whs = sm;                     // [512][16]: [k][u*4+q]
    float* hs  = sm + WHS_F;             // [32][HS_STRIDE]
    float* red = sm + WHS_F + HS_F;      // [8 s][32 tm * 16 gatecols]

    const int tid = threadIdx.x;
    const int u   = tid & 3;             // unit 0..3
    const int tmg = (tid >> 2) & 7;      // batch group (4 rows each)
    const int s   = tid >> 5;            // k-slice 0..7 (== warp id)
    const int tmb = tmg * 4;
    const int k0  = s * 64;
    const int j0  = blockIdx.x * 4;
    const unsigned nb = gridDim.x;

    // Load Wh slice: Whs[k*16 + uu*4 + q] = Wh[k][q*HH + j0 + uu]
    for (int idx = tid; idx < WHS_F; idx += 256) {
        int k = idx >> 4, c = idx & 15, uu = c >> 2, q = c & 3;
        Whs[idx] = Wh[(size_t)k * G4 + q * HH + j0 + uu];
    }

    // Update-thread state (threads 0..127: thread r handles (tm=r>>2, unit=r&3))
    float cst = 0.f;
    const int utm = tid >> 2;            // valid for tid<128
    const int uj  = j0 + (tid & 3);
    float xi = 0.f, xf = 0.f, xG = 0.f, xo = 0.f;
    if (tid < 128) {
        const float* xgp = g_xg + ((size_t)utm * SB + 0) * G4;
        xi = __ldcg(xgp + uj);          xf = __ldcg(xgp + HH + uj);
        xG = __ldcg(xgp + 2 * HH + uj); xo = __ldcg(xgp + 3 * HH + uj);
    }

    const float* hp0 = hs + (tmb + 0) * HS_STRIDE + k0;
    const float* hp1 = hs + (tmb + 1) * HS_STRIDE + k0;
    const float* hp2 = hs + (tmb + 2) * HS_STRIDE + k0;
    const float* hp3 = hs + (tmb + 3) * HS_STRIDE + k0;
    const float* wp  = Whs + k0 * 16 + u * 4;
    float* rwr = red + s * 512 + tmb * 16 + u * 4;   // this thread's partials

    for (int t = 0; t < SB; t++) {
        // ---- stage h[t-1] into SMEM (padded stride, conflict-free) ----
        if (t == 0) {
            float4 z = make_float4(0.f, 0.f, 0.f, 0.f);
            for (int i = tid; i < BH / 4; i += 256) {
                int m = i >> 7, c = i & 127;
                *(float4*)(hs + m * HS_STRIDE + (c << 2)) = z;
            }
        } else {
            const float4* src = (const float4*)(g_h + (size_t)(t - 1) * BH);
            for (int i = tid; i < BH / 4; i += 256) {
                int m = i >> 7, c = i & 127;
                *(float4*)(hs + m * HS_STRIDE + (c << 2)) = __ldcg(src + m * 128 + c);
            }
        }
        __syncthreads();

        // ---- GEMV: 4 batches x 4 gates over k in [k0, k0+64) ----
        unsigned long long a00 = 0, a01 = 0, a10 = 0, a11 = 0,
                           a20 = 0, a21 = 0, a30 = 0, a31 = 0;

#pragma unroll 4
        for (int kk = 0; kk < 64; kk += 4) {
            float4 ha = *(const float4*)(hp0 + kk);
            float4 hb = *(const float4*)(hp1 + kk);
            float4 hc = *(const float4*)(hp2 + kk);
            float4 hd = *(const float4*)(hp3 + kk);
            ulonglong2 w0 = *(const ulonglong2*)(wp + (kk + 0) * 16);
            ulonglong2 w1 = *(const ulonglong2*)(wp + (kk + 1) * 16);
            ulonglong2 w2 = *(const ulonglong2*)(wp + (kk + 2) * 16);
            ulonglong2 w3 = *(const ulonglong2*)(wp + (kk + 3) * 16);

            { unsigned long long d = dup2(ha.x); ffma2(a00, d, w0.x); ffma2(a01, d, w0.y); }
            { unsigned long long d = dup2(hb.x); ffma2(a10, d, w0.x); ffma2(a11, d, w0.y); }
            { unsigned long long d = dup2(hc.x); ffma2(a20, d, w0.x); ffma2(a21, d, w0.y); }
            { unsigned long long d = dup2(hd.x); ffma2(a30, d, w0.x); ffma2(a31, d, w0.y); }

            { unsigned long long d = dup2(ha.y); ffma2(a00, d, w1.x); ffma2(a01, d, w1.y); }
            { unsigned long long d = dup2(hb.y); ffma2(a10, d, w1.x); ffma2(a11, d, w1.y); }
            { unsigned long long d = dup2(hc.y); ffma2(a20, d, w1.x); ffma2(a21, d, w1.y); }
            { unsigned long long d = dup2(hd.y); ffma2(a30, d, w1.x); ffma2(a31, d, w1.y); }

            { unsigned long long d = dup2(ha.z); ffma2(a00, d, w2.x); ffma2(a01, d, w2.y); }
            { unsigned long long d = dup2(hb.z); ffma2(a10, d, w2.x); ffma2(a11, d, w2.y); }
            { unsigned long long d = dup2(hc.z); ffma2(a20, d, w2.x); ffma2(a21, d, w2.y); }
            { unsigned long long d = dup2(hd.z); ffma2(a30, d, w2.x); ffma2(a31, d, w2.y); }

            { unsigned long long d = dup2(ha.w); ffma2(a00, d, w3.x); ffma2(a01, d, w3.y); }
            { unsigned long long d = dup2(hb.w); ffma2(a10, d, w3.x); ffma2(a11, d, w3.y); }
            { unsigned long long d = dup2(hc.w); ffma2(a20, d, w3.x); ffma2(a21, d, w3.y); }
            { unsigned long long d = dup2(hd.w); ffma2(a30, d, w3.x); ffma2(a31, d, w3.y); }
        }

        // ---- write partials: red[s][(tmb+i)*16 + u*4 .. +3] ----
        {
            float p0, p1, p2, p3;
            unpack2(a00, p0, p1); unpack2(a01, p2, p3);
            *(float4*)(rwr + 0 * 16) = make_float4(p0, p1, p2, p3);
            unpack2(a10, p0, p1); unpack2(a11, p2, p3);
            *(float4*)(rwr + 1 * 16) = make_float4(p0, p1, p2, p3);
            unpack2(a20, p0, p1); unpack2(a21, p2, p3);
            *(float4*)(rwr + 2 * 16) = make_float4(p0, p1, p2, p3);
            unpack2(a30, p0, p1); unpack2(a31, p2, p3);
            *(float4*)(rwr + 3 * 16) = make_float4(p0, p1, p2, p3);
        }
        __syncthreads();

        // ---- 8-way reduction + cell update (threads 0..127) ----
        if (tid < 128) {
            const float* q = red + tid * 4;   // == utm*16 + uu*4
            float gi = xi, gf = xf, gg = xG, go = xo;
#pragma unroll
            for (int ss = 0; ss < 8; ss++) {
                float4 p = *(const float4*)(q + ss * 512);
                gi += p.x; gf += p.y; gg += p.z; go += p.w;
            }
            float si = sigm(gi), sf = sigm(gf), so = sigm(go);
            cst = sf * cst + si * tanhf(gg);
            float hn = so * tanhf(cst);
            __stcg(g_h + (size_t)t * BH + (size_t)utm * HH + uj, hn);

            // prefetch xg for step t+1 (hidden behind the barrier)
            int tn1 = (t + 1 < SB) ? (t + 1) : (SB - 1);
            const float* xgp = g_xg + ((size_t)utm * SB + tn1) * G4;
            xi = __ldcg(xgp + uj);          xf = __ldcg(xgp + HH + uj);
            xG = __ldcg(xgp + 2 * HH + uj); xo = __ldcg(xgp + 3 * HH + uj);
        }

        // ---- grid barrier (sense-reversing; bounded spin + sleep fallback) ----
        __threadfence();
        __syncthreads();
        if (tid == 0) {
            volatile unsigned* vgen = &g_bar_gen;
            unsigned g = *vgen;
            unsigned old = atomicAdd(&g_bar_cnt, 1u);
            if (old == nb - 1u) {
                atomicExch(&g_bar_cnt, 0u);
                __threadfence();
                atomicAdd(&g_bar_gen, 1u);
            } else {
                int spins = 0;
                while (*vgen == g) {
                    if (++spins >= 4096) { __nanosleep(64); spins = 0; }
                }
            }
        }
        __syncthreads();
    }
}

// ---------------------------------------------------------------------------
// Launch
// ---------------------------------------------------------------------------
extern "C" void kernel_launch(void* const* d_in, const int* in_sizes, int n_in,
                              void* d_out, int out_size) {
    const float *x = nullptr, *Wx = nullptr, *Wh = nullptr,
                *b = nullptr, *Wo = nullptr, *bo = nullptr;
    for (int i = 0; i < n_in; i++) {
        switch (in_sizes[i]) {
            case BB * SB * DD: x  = (const float*)d_in[i]; break;
            case DD * G4:      Wx = (const float*)d_in[i]; break;
            case HH * G4:      Wh = (const float*)d_in[i]; break;
            case G4:           b  = (const float*)d_in[i]; break;
            case HH * OO:      Wo = (const float*)d_in[i]; break;
            case OO:           bo = (const float*)d_in[i]; break;
        }
    }

    float* xg;   cudaGetSymbolAddress((void**)&xg, g_xg);
    float* hall; cudaGetSymbolAddress((void**)&hall, g_h);

    // 1) xg = x @ Wx + b
    {
        dim3 grid(G4 / 64, (BB * SB) / 64);
        sgemm_f32x2<false><<<grid, 128>>>(x, Wx, b, xg, BB * SB, G4, DD);
    }

    // 2 dummies so ncu's "-s 5 -c 1" window (2 hidden leading launches
    // observed) lands exactly on lstm_rec.
    dummy_k<<<1, 32>>>();
    dummy_k<<<1, 32>>>();

    // 2) persistent recurrence
    {
        int smem_bytes = (WHS_F + HS_F + RED_F) * (int)sizeof(float); // 115200
        cudaFuncSetAttribute(lstm_rec, cudaFuncAttributeMaxDynamicSharedMemorySize,
                             smem_bytes);
        lstm_rec<<<HH / 4, 256, smem_bytes>>>(Wh);
    }

    // 3) y = h @ Wo + bo with [t][b] -> [b][t] remap
    {
        dim3 grid(OO / 64, (BB * SB) / 64);
        sgemm_f32x2<true><<<grid, 128>>>(hall, Wo, bo, (float*)d_out,
                                         BB * SB, OO, HH);
    }
}